// round 3
// baseline (speedup 1.0000x reference)
#include <cuda_runtime.h>

// C51 categorical projection.
// reward [BS], probs [BS,51], not_done [BS] -> new_probs [BS,51]
//
// b(j) = clamp(c + s*j, 0, 50),  s = 0.99*nd,  c = 2.5*(reward + 10 - 10*s)
// floor(b) nondecreasing in j, step in {0,1}: two live bins in registers,
// bin emitted (predicated single STS) when k advances.
//
// SMEM: one region [256 rows][stride 52 floats] (16B-aligned rows; LDS.128
// phase-conflict-free: banks 20*t mod 32 are distinct per 8-lane phase).
// Reused in place: full row prefetched to registers, then zeroed + scattered.

constexpr int A   = 51;
constexpr int RPB = 256;
constexpr int RS  = 52;                         // padded row stride (floats)
constexpr int V4  = (RPB * A) / 4;              // 3264 float4 per block
constexpr int SMEM_BYTES = RPB * RS * (int)sizeof(float);  // 53248

__global__ __launch_bounds__(RPB, 3)
void cat_proj_kernel(const float4* __restrict__ probs4,
                     const float* __restrict__ reward,
                     const float* __restrict__ not_done,
                     float4* __restrict__ out4,
                     int bs)
{
    extern __shared__ float sm[];
    const int tid   = threadIdx.x;
    const int rbase = blockIdx.x * RPB;
    const long vbase = (long)blockIdx.x * V4;
    const long n4   = ((long)bs * A) / 4;

    // per-row scalars early (overlap with staging)
    const int grow = rbase + tid;
    float rw = 0.0f, nd = 0.0f;
    if (grow < bs) { rw = reward[grow]; nd = not_done[grow]; }

    // ── stage: coalesced float4 global reads, scalar smem stores (row-wrap aware)
    #pragma unroll
    for (int it = 0; it < 13; it++) {
        int idx = tid + it * RPB;
        if (idx < V4 && (vbase + idx) < n4) {
            float4 v = probs4[vbase + idx];
            int e = idx * 4;
            int r = e / A, col = e - r * A;
            int addr = r * RS + col;
            sm[addr] = v.x;
            col++; addr++; if (col == A) { r++; col = 0; addr = r * RS; }
            sm[addr] = v.y;
            col++; addr++; if (col == A) { r++; col = 0; addr = r * RS; }
            sm[addr] = v.z;
            col++; addr++; if (col == A) { r++; col = 0; addr = r * RS; }
            sm[addr] = v.w;
        }
    }
    __syncthreads();

    float* row = sm + tid * RS;

    if (grow < bs) {
        // ── prefetch own row: 12x LDS.128 + 3x LDS.32 (conflict-free phases)
        float pv[A];
        #pragma unroll
        for (int q = 0; q < 12; q++) {
            float4 v = *(const float4*)(row + 4 * q);
            pv[4*q] = v.x; pv[4*q+1] = v.y; pv[4*q+2] = v.z; pv[4*q+3] = v.w;
        }
        pv[48] = row[48]; pv[49] = row[49]; pv[50] = row[50];

        // ── zero own row in place (reads done): 13x STS.128
        float4 z = make_float4(0.f, 0.f, 0.f, 0.f);
        #pragma unroll
        for (int q = 0; q < 13; q++)
            *(float4*)(row + 4 * q) = z;

        // ── scan
        const float s = 0.99f * nd;
        const float c = 2.5f * (rw + 10.0f - 10.0f * s);

        float b  = fminf(fmaxf(c, 0.0f), 50.0f);
        float lf = floorf(b);
        int   k  = (int)lf;
        float wu = (b - lf) * pv[0];
        float aK  = pv[0] - wu;
        float aK1 = wu;

        #pragma unroll
        for (int j = 1; j < A; j++) {
            b  = fminf(fmaxf(fmaf(s, (float)j, c), 0.0f), 50.0f);
            lf = floorf(b);
            int li = (int)lf;                 // in {k, k+1}
            wu = (b - lf) * pv[j];
            float wl = pv[j] - wu;

            bool adv = (li != k);
            if (adv) row[k] = aK;             // predicated single STS
            aK  = adv ? aK1  : aK;
            aK1 = adv ? 0.0f : aK1;
            k   = li;

            aK  += wl;
            aK1 += wu;
        }
        // final emits; if k==50 then aK1==0 and the overwrite is benign
        int k1 = k + 1; if (k1 > A - 1) k1 = A - 1;
        row[k1] = aK1;
        row[k]  = aK;
    }
    __syncthreads();

    // ── copy out: scalar smem reads (near-conflict-free), float4 global stores
    #pragma unroll
    for (int it = 0; it < 13; it++) {
        int idx = tid + it * RPB;
        if (idx < V4 && (vbase + idx) < n4) {
            int e = idx * 4;
            int r = e / A, col = e - r * A;
            int addr = r * RS + col;
            float4 v;
            v.x = sm[addr];
            col++; addr++; if (col == A) { r++; col = 0; addr = r * RS; }
            v.y = sm[addr];
            col++; addr++; if (col == A) { r++; col = 0; addr = r * RS; }
            v.z = sm[addr];
            col++; addr++; if (col == A) { r++; col = 0; addr = r * RS; }
            v.w = sm[addr];
            out4[vbase + idx] = v;
        }
    }
}

extern "C" void kernel_launch(void* const* d_in, const int* in_sizes, int n_in,
                              void* d_out, int out_size)
{
    const float*  reward   = (const float*)d_in[0];
    const float4* probs4   = (const float4*)d_in[1];
    const float*  not_done = (const float*)d_in[2];
    float4* out4 = (float4*)d_out;

    const int bs = in_sizes[0];
    const int grid = (bs + RPB - 1) / RPB;

    cudaFuncSetAttribute(cat_proj_kernel,
                         cudaFuncAttributeMaxDynamicSharedMemorySize,
                         SMEM_BYTES);
    cat_proj_kernel<<<grid, RPB, SMEM_BYTES>>>(probs4, reward, not_done, out4, bs);
}